// round 8
// baseline (speedup 1.0000x reference)
#include <cuda_runtime.h>

typedef unsigned long long ull;

#define BMAX 16384

__device__ float g_y2[BMAX * 400];    // conv2+pool output, flattened (C,H,W)
__device__ float g_w1T[400 * 128];    // fc_w packed  [k/4][c][4]
__device__ float g_w2T[128 * 64];     // fc2_w packed [k/4][c][4]

__device__ __forceinline__ float4 fma4(float4 a, float4 b, float4 c) {
    return make_float4(fmaf(a.x, b.x, c.x), fmaf(a.y, b.y, c.y),
                       fmaf(a.z, b.z, c.z), fmaf(a.w, b.w, c.w));
}
__device__ __forceinline__ ull ffma2(ull a, ull b, ull c) {
    ull d; asm("fma.rn.f32x2 %0, %1, %2, %3;" : "=l"(d) : "l"(a), "l"(b), "l"(c)); return d;
}
__device__ __forceinline__ void upk(ull v, float& lo, float& hi) {
    asm("mov.b64 {%0, %1}, %2;" : "=f"(lo), "=f"(hi) : "l"(v));
}

// ---------------------------------------------------------------------------
// Weight repack: w1T[(k/4)][c][4] so k3 loads 4 k-weights per LDG.128.
// ---------------------------------------------------------------------------
__global__ void __launch_bounds__(256) kT(const float* __restrict__ fc_w,
                                          const float* __restrict__ fc2_w) {
    const int i = blockIdx.x * 256 + threadIdx.x;
    if (i < 51200) {
        const int c = i / 400, k = i - c * 400;
        g_w1T[(k >> 2) * 512 + c * 4 + (k & 3)] = fc_w[i];
    }
    if (i < 8192) {
        const int c = i / 128, k = i - c * 128;
        g_w2T[(k >> 2) * 256 + c * 4 + (k & 3)] = fc2_w[i];
    }
}

// ---------------------------------------------------------------------------
// Fused conv kernel, 2 images / 160 threads.
// ---------------------------------------------------------------------------
__global__ void __launch_bounds__(160) k12_conv(const float* __restrict__ x,
                                                const float* __restrict__ w1,
                                                const float* __restrict__ b1,
                                                const float* __restrict__ w2,
                                                const float* __restrict__ b2) {
    __shared__ __align__(16) float SM[8888];
    float*  Tbuf = SM;                   // [2 img][12 y][8 ic][5 p][4] = 3840
    float*  sx   = SM;                   // [2 img][784] (alias, disjoint lifetime)
    float*  sy1  = SM + 3840;            // [2 img][8 ic][13 y][16] = 3328
    float4* suw4 = (float4*)(SM + 7168); // [16 oc][25] float4
    float4* sw14 = (float4*)(SM + 8768); // [8 oc][3 ky] float4 (w0,w1,w2,0)
    float*  sb1  = SM + 8864;
    float*  sb2  = SM + 8872;

    const int img0 = blockIdx.x * 2;
    const int t = threadIdx.x;

    // ---- stage 0 ----
    if (t < 24) {
        const int oc = t / 3, ky = t - oc * 3;
        const float* g = w1 + oc * 9 + ky * 3;
        sw14[t] = make_float4(g[0], g[1], g[2], 0.f);
    }
    if (t >= 80 && t < 88)   sb1[t - 80] = b1[t - 80];
    if (t >= 88 && t < 104)  sb2[t - 88] = b2[t - 88];
    for (int i = t; i < 384; i += 160) {         // Winograd weight transform
        const int oc = i / 24, rem = i - oc * 24;
        const int ic = rem / 3, ky = rem - ic * 3;
        const float* g = w2 + oc * 72 + ic * 9 + ky * 3;
        const float a = g[0], bq = g[1], c = g[2];
        suw4[oc * 25 + ic * 3 + ky] =
            make_float4(a, 0.5f * (a + bq + c), 0.5f * (a - bq + c), c);
    }
    {
        const float4* xs = (const float4*)(x + img0 * 784);
        for (int i = t; i < 392; i += 160) ((float4*)sx)[i] = xs[i];
    }
    __syncthreads();

    // ---- phase A: conv1 + bias + relu + pool -> sy1 ----
    for (int i = t; i < 338; i += 160) {
        const int sub = i / 169;
        const int local = i - sub * 169;
        const int py = local / 13, px = local - py * 13;
        const float* xim = sx + sub * 784 + (2 * py) * 28 + 2 * px;

        float win[4][4];
#pragma unroll
        for (int j = 0; j < 4; j++) {
            const float2* rr = (const float2*)(xim + j * 28);
            const float2 a = rr[0], b = rr[1];
            win[j][0] = a.x; win[j][1] = a.y; win[j][2] = b.x; win[j][3] = b.y;
        }

        float* outp = sy1 + sub * 1664 + py * 16 + px;
#pragma unroll
        for (int oc = 0; oc < 8; oc++) {
            float c00 = 0.f, c01 = 0.f, c10 = 0.f, c11 = 0.f;
#pragma unroll
            for (int ky = 0; ky < 3; ky++) {
                const float4 wv = sw14[oc * 3 + ky];
                c00 = fmaf(win[ky][0], wv.x, c00);
                c00 = fmaf(win[ky][1], wv.y, c00);
                c00 = fmaf(win[ky][2], wv.z, c00);
                c01 = fmaf(win[ky][1], wv.x, c01);
                c01 = fmaf(win[ky][2], wv.y, c01);
                c01 = fmaf(win[ky][3], wv.z, c01);
                c10 = fmaf(win[ky + 1][0], wv.x, c10);
                c10 = fmaf(win[ky + 1][1], wv.y, c10);
                c10 = fmaf(win[ky + 1][2], wv.z, c10);
                c11 = fmaf(win[ky + 1][1], wv.x, c11);
                c11 = fmaf(win[ky + 1][2], wv.y, c11);
                c11 = fmaf(win[ky + 1][3], wv.z, c11);
            }
            const float m = fmaxf(fmaxf(c00, c01), fmaxf(c10, c11)) + sb1[oc];
            outp[oc * 208] = fmaxf(m, 0.f);
        }
    }
    __syncthreads();

    // ---- phase B1: input transform (rows 0..11, shared across 16 oc) ----
    for (int i = t; i < 192; i += 160) {
        const int img = i / 96, rem = i - img * 96;
        const int y = rem / 8, ic = rem - y * 8;
        const float4* rp = (const float4*)(sy1 + img * 1664 + ic * 208 + y * 16);
        float r[12];
#pragma unroll
        for (int m = 0; m < 3; m++) {
            const float4 v = rp[m];
            r[4 * m] = v.x; r[4 * m + 1] = v.y; r[4 * m + 2] = v.z; r[4 * m + 3] = v.w;
        }
        float4* dst = (float4*)(Tbuf + img * 1920 + (y * 8 + ic) * 20);
#pragma unroll
        for (int p = 0; p < 5; p++)
            dst[p] = make_float4(r[2 * p] - r[2 * p + 2],
                                 r[2 * p + 1] + r[2 * p + 2],
                                 r[2 * p + 2] - r[2 * p + 1],
                                 r[2 * p + 1] - r[2 * p + 3]);
    }
    __syncthreads();

    // ---- phase B2: m-space conv2 + pool + bias + relu ----
    const int sub = t / 80;
    const int r = t - sub * 80;
    const int py = r >> 4, oc = r & 15;
    const float* Timg = Tbuf + sub * 1920;
    const float4* wbase = suw4 + oc * 25;

    float4 macc[2][5];
#pragma unroll
    for (int a = 0; a < 2; a++)
#pragma unroll
        for (int p = 0; p < 5; p++) macc[a][p] = make_float4(0.f, 0.f, 0.f, 0.f);

#pragma unroll 2
    for (int ic = 0; ic < 8; ic++) {
        const float4 u0 = wbase[ic * 3 + 0];
        const float4 u1 = wbase[ic * 3 + 1];
        const float4 u2 = wbase[ic * 3 + 2];
#pragma unroll
        for (int s = 0; s < 4; s++) {
            const float4* Trow = (const float4*)(Timg + ((2 * py + s) * 8 + ic) * 20);
            float4 tr[5];
#pragma unroll
            for (int p = 0; p < 5; p++) tr[p] = Trow[p];
            if (s < 3) {
                const float4 u = (s == 0) ? u0 : (s == 1) ? u1 : u2;
#pragma unroll
                for (int p = 0; p < 5; p++) macc[0][p] = fma4(tr[p], u, macc[0][p]);
            }
            if (s >= 1) {
                const float4 u = (s == 1) ? u0 : (s == 2) ? u1 : u2;
#pragma unroll
                for (int p = 0; p < 5; p++) macc[1][p] = fma4(tr[p], u, macc[1][p]);
            }
        }
    }

    float* outp = g_y2 + (img0 + sub) * 400 + oc * 25 + py * 5;
    const float bb = sb2[oc];
#pragma unroll
    for (int p = 0; p < 5; p++) {
        const float o00 = macc[0][p].x + macc[0][p].y + macc[0][p].z;
        const float o01 = macc[0][p].y - macc[0][p].z - macc[0][p].w;
        const float o10 = macc[1][p].x + macc[1][p].y + macc[1][p].z;
        const float o11 = macc[1][p].y - macc[1][p].z - macc[1][p].w;
        const float m = fmaxf(fmaxf(o00, o01), fmaxf(o10, o11));
        outp[p] = fmaxf(m + bb, 0.f);
    }
}

// ---------------------------------------------------------------------------
// Kernel 3: fc layers with fma.rn.f32x2 (clean test: zero pack instructions —
// all packed operands come directly from 16B loads reinterpreted as ulonglong2).
// ---------------------------------------------------------------------------
__global__ void __launch_bounds__(128) k3_fc(const float* __restrict__ fc_b,
                                             const float* __restrict__ fc2_b,
                                             const float* __restrict__ fc3_w,
                                             const float* __restrict__ fc3_b,
                                             float* __restrict__ out) {
    __shared__ __align__(16) float sx[16 * 400];
    __shared__ __align__(16) float sh1[16 * 128];
    __shared__ __align__(16) float sh2[16 * 64];
    __shared__ __align__(16) float sw3[640];
    __shared__ float sb3[10];

    const int r0 = blockIdx.x * 16;
    const int t = threadIdx.x;

    {
        const float4* xin = (const float4*)(g_y2 + r0 * 400);
        for (int i = t; i < 1600; i += 128) ((float4*)sx)[i] = xin[i];
        for (int i = t; i < 160; i += 128) ((float4*)sw3)[i] = ((const float4*)fc3_w)[i];
        if (t < 10) sb3[t] = fc3_b[t];
    }
    __syncthreads();

    // ---- stage 1: h1[r][t] = relu(X[r] . W1[:,t] + fc_b[t]) ----
    {
        ull acc[16];
#pragma unroll
        for (int r = 0; r < 16; r++) acc[r] = 0ull;
        const ulonglong2* wp = (const ulonglong2*)g_w1T + t;   // [k4][128] 16B units
#pragma unroll 2
        for (int k4 = 0; k4 < 100; k4++) {
            const ulonglong2 w2v = wp[k4 * 128];
#pragma unroll
            for (int r = 0; r < 16; r++) {
                const ulonglong2 x2 = ((const ulonglong2*)sx)[r * 100 + k4];
                acc[r] = ffma2(x2.x, w2v.x, acc[r]);
                acc[r] = ffma2(x2.y, w2v.y, acc[r]);
            }
        }
        const float bb = fc_b[t];
#pragma unroll
        for (int r = 0; r < 16; r++) {
            float lo, hi; upk(acc[r], lo, hi);
            sh1[r * 128 + t] = fmaxf(lo + hi + bb, 0.f);
        }
    }
    __syncthreads();

    // ---- stage 2: h2[r][c] = h1[r] . W2[:,c] + fc2_b[c] ----
    {
        const int c = t & 63;
        const int rbase = (t >> 6) * 8;
        ull acc[8];
#pragma unroll
        for (int r = 0; r < 8; r++) acc[r] = 0ull;
        const ulonglong2* wp = (const ulonglong2*)g_w2T + c;   // [k4][64] 16B units
#pragma unroll 4
        for (int k4 = 0; k4 < 32; k4++) {
            const ulonglong2 w2v = wp[k4 * 64];
#pragma unroll
            for (int r = 0; r < 8; r++) {
                const ulonglong2 h2v = ((const ulonglong2*)sh1)[(rbase + r) * 32 + k4];
                acc[r] = ffma2(h2v.x, w2v.x, acc[r]);
                acc[r] = ffma2(h2v.y, w2v.y, acc[r]);
            }
        }
        const float bb = fc2_b[c];
#pragma unroll
        for (int r = 0; r < 8; r++) {
            float lo, hi; upk(acc[r], lo, hi);
            sh2[(rbase + r) * 64 + c] = lo + hi + bb;
        }
    }
    __syncthreads();

    // ---- stage 3 ----
    for (int idx = t; idx < 160; idx += 128) {
        const int r = idx / 10, c = idx - r * 10;
        ull acc = 0ull;
        const ulonglong2* h = (const ulonglong2*)(sh2 + r * 64);
        const ulonglong2* wv = (const ulonglong2*)(sw3 + c * 64);
#pragma unroll
        for (int k = 0; k < 16; k++) {
            acc = ffma2(h[k].x, wv[k].x, acc);
            acc = ffma2(h[k].y, wv[k].y, acc);
        }
        float lo, hi; upk(acc, lo, hi);
        out[(r0 + r) * 10 + c] = lo + hi + sb3[c];
    }
}

// ---------------------------------------------------------------------------
extern "C" void kernel_launch(void* const* d_in, const int* in_sizes, int n_in,
                              void* d_out, int out_size) {
    const float* x       = (const float*)d_in[0];
    const float* conv1_w = (const float*)d_in[1];
    const float* conv1_b = (const float*)d_in[2];
    const float* conv2_w = (const float*)d_in[3];
    const float* conv2_b = (const float*)d_in[4];
    const float* fc_w    = (const float*)d_in[5];
    const float* fc_b    = (const float*)d_in[6];
    const float* fc2_w   = (const float*)d_in[7];
    const float* fc2_b   = (const float*)d_in[8];
    const float* fc3_w   = (const float*)d_in[9];
    const float* fc3_b   = (const float*)d_in[10];
    float* out = (float*)d_out;

    const int B = in_sizes[0] / 784;

    kT<<<200, 256>>>(fc_w, fc2_w);
    k12_conv<<<B / 2, 160>>>(x, conv1_w, conv1_b, conv2_w, conv2_b);
    k3_fc<<<B / 16, 128>>>(fc_b, fc2_b, fc3_w, fc3_b, out);
}